// round 5
// baseline (speedup 1.0000x reference)
#include <cuda_runtime.h>
#include <math.h>
#include <stdint.h>

// Problem constants
#define Bc   2
#define Mc   2048
#define Dc   1024
#define Hc   16
#define DHc  64
#define FFc  2624
#define ROWS (Bc * Mc)      // 4096
#define QKVN (3 * Dc)       // 3072
#define WIN  (2 * FFc)      // 5248

// ---------------- scratch (device globals; no cudaMalloc allowed) ----------------
__device__ __align__(16) float g_xn  [ROWS * Dc];
__device__ __align__(16) float g_qkv [ROWS * QKVN];
__device__ __align__(16) float g_attn[ROWS * Dc];
__device__ __align__(16) float g_x1  [ROWS * Dc];
__device__ __align__(16) float g_h   [ROWS * Dc];
__device__ __align__(16) float g_g   [(size_t)ROWS * WIN];
__device__ __align__(16) float g_act [(size_t)ROWS * FFc];

// ---------------- packed f32x2 helpers (Blackwell FFMA2) ----------------
__device__ __forceinline__ uint64_t splat2(float v) {
    uint64_t r; asm("mov.b64 %0, {%1,%1};" : "=l"(r) : "f"(v)); return r;
}
__device__ __forceinline__ void unpack2(float& lo, float& hi, uint64_t v) {
    asm("mov.b64 {%0,%1}, %2;" : "=f"(lo), "=f"(hi) : "l"(v));
}
__device__ __forceinline__ void fma2(uint64_t& d, uint64_t a, uint64_t b) {
    asm("fma.rn.f32x2 %0, %1, %2, %0;" : "+l"(d) : "l"(a), "l"(b));
}
__device__ __forceinline__ uint64_t mul2(uint64_t a, uint64_t b) {
    uint64_t r; asm("mul.rn.f32x2 %0, %1, %2;" : "=l"(r) : "l"(a), "l"(b)); return r;
}
// 16B shared load producing two packed f32x2 operands
__device__ __forceinline__ void lds2(uint64_t& x, uint64_t& y, const float* p) {
    uint32_t a = (uint32_t)__cvta_generic_to_shared(p);
    asm volatile("ld.shared.v2.u64 {%0,%1}, [%2];" : "=l"(x), "=l"(y) : "r"(a));
}

// ======== FFMA2 NT SGEMM: C[M,Nd] = A[M,Kd] @ B[Nd,Kd]^T (+bias)(+res) ========
// BM=BN=128, BK=16, 256 threads, 8x8 per thread (acc packed in pairs along N).
__global__ void __launch_bounds__(256) gemm_nt(const float* __restrict__ A,
                                               const float* __restrict__ Bw,
                                               const float* __restrict__ bias,
                                               const float* __restrict__ res,
                                               float* __restrict__ C,
                                               int Nd, int Kd) {
    __shared__ __align__(16) float As[16][128];
    __shared__ __align__(16) float Bs[16][128];

    int n0 = blockIdx.x * 128;
    int m0 = blockIdx.y * 128;
    int t  = threadIdx.x;
    int tx = t & 15, ty = t >> 4;

    int lrow = t >> 1;           // 0..127
    int lcol = (t & 1) * 8;      // 0 or 8

    const float* Ap = A  + (size_t)(m0 + lrow) * Kd + lcol;
    const float* Bp = Bw + (size_t)(n0 + lrow) * Kd + lcol;

    uint64_t acc[8][4];
    #pragma unroll
    for (int r = 0; r < 8; r++)
        #pragma unroll
        for (int c = 0; c < 4; c++) acc[r][c] = 0ull;

    // prefetch first k-slab
    float4 pa0 = *(const float4*)(Ap);
    float4 pa1 = *(const float4*)(Ap + 4);
    float4 pb0 = *(const float4*)(Bp);
    float4 pb1 = *(const float4*)(Bp + 4);

    const int nch = Kd >> 4;
    for (int i = 0; i < nch; i++) {
        __syncthreads();
        As[lcol + 0][lrow] = pa0.x; As[lcol + 1][lrow] = pa0.y;
        As[lcol + 2][lrow] = pa0.z; As[lcol + 3][lrow] = pa0.w;
        As[lcol + 4][lrow] = pa1.x; As[lcol + 5][lrow] = pa1.y;
        As[lcol + 6][lrow] = pa1.z; As[lcol + 7][lrow] = pa1.w;
        Bs[lcol + 0][lrow] = pb0.x; Bs[lcol + 1][lrow] = pb0.y;
        Bs[lcol + 2][lrow] = pb0.z; Bs[lcol + 3][lrow] = pb0.w;
        Bs[lcol + 4][lrow] = pb1.x; Bs[lcol + 5][lrow] = pb1.y;
        Bs[lcol + 6][lrow] = pb1.z; Bs[lcol + 7][lrow] = pb1.w;
        __syncthreads();

        if (i + 1 < nch) {
            int k0 = (i + 1) << 4;
            pa0 = *(const float4*)(Ap + k0);
            pa1 = *(const float4*)(Ap + k0 + 4);
            pb0 = *(const float4*)(Bp + k0);
            pb1 = *(const float4*)(Bp + k0 + 4);
        }

        #pragma unroll
        for (int k = 0; k < 16; k++) {
            float ar[8];
            *reinterpret_cast<float4*>(ar)     = *reinterpret_cast<float4*>(&As[k][ty * 8]);
            *reinterpret_cast<float4*>(ar + 4) = *reinterpret_cast<float4*>(&As[k][ty * 8 + 4]);
            uint64_t bp[4];
            lds2(bp[0], bp[1], &Bs[k][tx * 8]);
            lds2(bp[2], bp[3], &Bs[k][tx * 8 + 4]);
            #pragma unroll
            for (int r = 0; r < 8; r++) {
                uint64_t a2 = splat2(ar[r]);
                fma2(acc[r][0], a2, bp[0]);
                fma2(acc[r][1], a2, bp[1]);
                fma2(acc[r][2], a2, bp[2]);
                fma2(acc[r][3], a2, bp[3]);
            }
        }
    }

    // epilogue: unpack, bias + residual, float2 stores
    #pragma unroll
    for (int r = 0; r < 8; r++) {
        int gm = m0 + ty * 8 + r;
        float* Cp = C + (size_t)gm * Nd + n0 + tx * 8;
        const float* Rp = res ? (res + (size_t)gm * Nd + n0 + tx * 8) : nullptr;
        #pragma unroll
        for (int p = 0; p < 4; p++) {
            float v0, v1;
            unpack2(v0, v1, acc[r][p]);
            if (bias) {
                v0 += bias[n0 + tx * 8 + 2 * p];
                v1 += bias[n0 + tx * 8 + 2 * p + 1];
            }
            if (Rp) {
                v0 += Rp[2 * p];
                v1 += Rp[2 * p + 1];
            }
            *(float2*)(Cp + 2 * p) = make_float2(v0, v1);
        }
    }
}

// ---------------- LayerNorm: one block per row, D=1024, 256 threads ----------------
__global__ void __launch_bounds__(256) ln_kernel(const float* __restrict__ x,
                                                 const float* __restrict__ w,
                                                 const float* __restrict__ b,
                                                 float* __restrict__ out) {
    int row = blockIdx.x;
    int t = threadIdx.x;
    const float4* xr = reinterpret_cast<const float4*>(x + (size_t)row * Dc);
    float4 v = xr[t];
    float s  = v.x + v.y + v.z + v.w;
    float ss = v.x * v.x + v.y * v.y + v.z * v.z + v.w * v.w;

    __shared__ float red0[8], red1[8];
    #pragma unroll
    for (int o = 16; o; o >>= 1) {
        s  += __shfl_xor_sync(0xffffffffu, s,  o);
        ss += __shfl_xor_sync(0xffffffffu, ss, o);
    }
    int wid = t >> 5, lid = t & 31;
    if (lid == 0) { red0[wid] = s; red1[wid] = ss; }
    __syncthreads();
    if (t == 0) {
        float a = 0.f, c = 0.f;
        #pragma unroll
        for (int i = 0; i < 8; i++) { a += red0[i]; c += red1[i]; }
        red0[0] = a; red1[0] = c;
    }
    __syncthreads();
    s = red0[0]; ss = red1[0];
    float mu   = s * (1.0f / Dc);
    float var  = ss * (1.0f / Dc) - mu * mu;
    float rstd = rsqrtf(var + 1e-5f);

    const float4* w4 = reinterpret_cast<const float4*>(w);
    const float4* b4 = reinterpret_cast<const float4*>(b);
    float4 ww = w4[t], bb = b4[t], o4;
    o4.x = (v.x - mu) * rstd * ww.x + bb.x;
    o4.y = (v.y - mu) * rstd * ww.y + bb.y;
    o4.z = (v.z - mu) * rstd * ww.z + bb.z;
    o4.w = (v.w - mu) * rstd * ww.w + bb.w;
    reinterpret_cast<float4*>(out + (size_t)row * Dc)[t] = o4;
}

// ---------------- RoPE (in-place on q,k slabs of qkv) ----------------
__global__ void rope_kernel(float* __restrict__ qkv) {
    int idx = blockIdx.x * blockDim.x + threadIdx.x;   // ROWS*H*32
    if (idx >= ROWS * Hc * (DHc / 2)) return;
    int j   = idx & 31;
    int h   = (idx >> 5) & (Hc - 1);
    int row = idx >> 9;
    int m   = row & (Mc - 1);

    float inv_freq = powf(10000.0f, -(float)(2 * j) / (float)DHc);
    float freq = (float)m * inv_freq;
    float sn, cs;
    sincosf(freq, &sn, &cs);

    float* qp = qkv + (size_t)row * QKVN + h * DHc;
    float* kp = qp + Dc;
    float q1 = qp[j], q2 = qp[32 + j];
    qp[j]      = q1 * cs - q2 * sn;
    qp[32 + j] = q1 * sn + q2 * cs;
    float k1 = kp[j], k2 = kp[32 + j];
    kp[j]      = k1 * cs - k2 * sn;
    kp[32 + j] = k1 * sn + k2 * cs;
}

// ---------------- Flash attention: swizzled smem + f32x2 ----------------
// 32 queries/block, 64-key tiles, 256 threads; thread (q = t>>3, kg = t&7).
#define QT 32
#define KT 64
// float offsets in dynamic smem
#define A_QS   0
#define A_KS   (A_QS + QT * 64)     // 2048
#define A_VS   (A_KS + KT * 64)     // 6144
#define A_PB   (A_VS + KT * 64)     // 10240
#define A_M    (A_PB + QT * 65)     // 12320
#define A_L    (A_M + QT)
#define A_SC   (A_L + QT)
#define A_MSK  (A_SC + QT)
#define A_FLOATS (A_MSK + KT)
#define ATTN_SMEM_BYTES (A_FLOATS * 4)

// swizzled float offset of (row, seg) in a [rows][64] tile: 16 segs of 4 floats
#define SWIDX(r, seg) ((r) * 64 + ((((seg) ^ ((r) & 7))) << 2))

__global__ void __launch_bounds__(256) attn_kernel(const float* __restrict__ qkv,
                                                   const int* __restrict__ mask,
                                                   float* __restrict__ out) {
    extern __shared__ __align__(16) float sh[];
    float* Qs  = sh + A_QS;
    float* Ks  = sh + A_KS;
    float* Vs  = sh + A_VS;
    float* Pb  = sh + A_PB;
    float* smM = sh + A_M;
    float* smL = sh + A_L;
    float* smS = sh + A_SC;
    int*   msk = reinterpret_cast<int*>(sh + A_MSK);

    int m0 = blockIdx.x * QT;
    int h  = blockIdx.y;
    int b  = blockIdx.z;
    int t  = threadIdx.x;

    const float* qbase = qkv + (size_t)(b * Mc + m0) * QKVN + h * DHc;
    const float* kbase = qkv + (size_t)(b * Mc) * QKVN + Dc + h * DHc;
    const float* vbase = kbase + Dc;
    const int*   mbase = mask + b * Mc;

    // load Q (pre-scaled), swizzled
    for (int idx = t; idx < QT * 16; idx += 256) {
        int q = idx >> 4, seg = idx & 15;
        float4 v = *(const float4*)(qbase + (size_t)q * QKVN + seg * 4);
        v.x *= 0.125f; v.y *= 0.125f; v.z *= 0.125f; v.w *= 0.125f;
        *(float4*)&Qs[SWIDX(q, seg)] = v;
    }
    if (t < QT) { smM[t] = -1e30f; smL[t] = 0.f; }

    const int q  = t >> 3;
    const int kg = t & 7;
    const int qx = q & 7;
    uint64_t o2[4] = {0ull, 0ull, 0ull, 0ull};

    for (int n0 = 0; n0 < Mc; n0 += KT) {
        __syncthreads();  // previous tile's Ks/Vs/Pb fully consumed
        for (int idx = t; idx < KT * 16; idx += 256) {
            int r = idx >> 4, seg = idx & 15;
            float4 kv = *(const float4*)(kbase + (size_t)(n0 + r) * QKVN + seg * 4);
            *(float4*)&Ks[SWIDX(r, seg)] = kv;
            float4 vv = *(const float4*)(vbase + (size_t)(n0 + r) * QKVN + seg * 4);
            *(float4*)&Vs[SWIDX(r, seg)] = vv;
        }
        if (t < KT) msk[t] = mbase[n0 + t];
        __syncthreads();

        // ---- scores for keys kk = kg + 8*i (f32x2: even/odd d lanes) ----
        uint64_t s2[8];
        #pragma unroll
        for (int i = 0; i < 8; i++) s2[i] = 0ull;
        const float* qrow = Qs + q * 64;
        #pragma unroll
        for (int seg = 0; seg < 16; seg++) {
            uint64_t q0, q1;
            lds2(q0, q1, qrow + ((seg ^ qx) << 2));
            #pragma unroll
            for (int i = 0; i < 8; i++) {
                uint64_t k0, k1;
                lds2(k0, k1, &Ks[(kg + 8 * i) * 64 + ((seg ^ kg) << 2)]);
                fma2(s2[i], q0, k0);
                fma2(s2[i], q1, k1);
            }
        }
        float s[8];
        #pragma unroll
        for (int i = 0; i < 8; i++) {
            float lo, hi; unpack2(lo, hi, s2[i]);
            s[i] = lo + hi;
        }

        bool valid[8];
        float mx = -1e30f;
        #pragma unroll
        for (int i = 0; i < 8; i++) {
            valid[i] = (msk[kg + 8 * i] != 0);
            if (valid[i]) mx = fmaxf(mx, s[i]);
        }
        mx = fmaxf(mx, __shfl_xor_sync(0xffffffffu, mx, 1));
        mx = fmaxf(mx, __shfl_xor_sync(0xffffffffu, mx, 2));
        mx = fmaxf(mx, __shfl_xor_sync(0xffffffffu, mx, 4));

        float m_old = smM[q];
        float m_new = fmaxf(m_old, mx);
        float scale = __expf(m_old - m_new);
        float psum = 0.f;
        #pragma unroll
        for (int i = 0; i < 8; i++) {
            float p = valid[i] ? __expf(s[i] - m_new) : 0.f;
            Pb[q * 65 + kg + 8 * i] = p;
            psum += p;
        }
        psum += __shfl_xor_sync(0xffffffffu, psum, 1);
        psum += __shfl_xor_sync(0xffffffffu, psum, 2);
        psum += __shfl_xor_sync(0xffffffffu, psum, 4);
        if (kg == 0) {
            smL[q] = smL[q] * scale + psum;
            smM[q] = m_new;
            smS[q] = scale;
        }
        __syncthreads();

        // ---- PV: thread owns dims d = kg*8 .. kg*8+7 (segs 2kg, 2kg+1) ----
        {
            uint64_t sc2 = splat2(smS[q]);
            #pragma unroll
            for (int j = 0; j < 4; j++) o2[j] = mul2(o2[j], sc2);
        }
        const float* prow = Pb + q * 65;
        #pragma unroll 4
        for (int kk = 0; kk < KT; kk++) {
            uint64_t p2 = splat2(prow[kk]);
            int c = kk & 7;
            const float* vrow = Vs + kk * 64;
            uint64_t v0, v1, v2, v3;
            lds2(v0, v1, vrow + (((2 * kg)     ^ c) << 2));
            lds2(v2, v3, vrow + (((2 * kg + 1) ^ c) << 2));
            fma2(o2[0], p2, v0);
            fma2(o2[1], p2, v1);
            fma2(o2[2], p2, v2);
            fma2(o2[3], p2, v3);
        }
    }
    __syncthreads();
    float inv_l = 1.0f / smL[q];
    float o[8];
    #pragma unroll
    for (int j = 0; j < 4; j++) {
        unpack2(o[2 * j], o[2 * j + 1], o2[j]);
        o[2 * j]     *= inv_l;
        o[2 * j + 1] *= inv_l;
    }
    float* op = out + (size_t)(b * Mc + m0 + q) * Dc + h * DHc + kg * 8;
    *(float4*)(op)     = make_float4(o[0], o[1], o[2], o[3]);
    *(float4*)(op + 4) = make_float4(o[4], o[5], o[6], o[7]);
}

// ---------------- GeGLU (exact gelu * gate) ----------------
__global__ void geglu_kernel(const float* __restrict__ g, float* __restrict__ act) {
    int idx = blockIdx.x * blockDim.x + threadIdx.x;
    if (idx >= ROWS * FFc) return;
    int r = idx / FFc;
    int j = idx - r * FFc;
    float x    = g[(size_t)r * WIN + j];
    float gate = g[(size_t)r * WIN + FFc + j];
    float ge = 0.5f * x * (1.0f + erff(x * 0.7071067811865476f));
    act[idx] = ge * gate;
}

// ---------------- launch ----------------
extern "C" void kernel_launch(void* const* d_in, const int* in_sizes, int n_in,
                              void* d_out, int out_size) {
    const float* x     = (const float*)d_in[0];
    const int*   mask  = (const int*)  d_in[1];
    const float* ln1w  = (const float*)d_in[2];
    const float* ln1b  = (const float*)d_in[3];
    const float* wqkv  = (const float*)d_in[4];
    const float* bqkv  = (const float*)d_in[5];
    const float* wo    = (const float*)d_in[6];
    const float* ln2w  = (const float*)d_in[7];
    const float* ln2b  = (const float*)d_in[8];
    const float* wi    = (const float*)d_in[9];
    const float* womlp = (const float*)d_in[10];
    float* out = (float*)d_out;

    float *xn, *qkvb, *attn, *x1, *hb, *gb, *actb;
    cudaGetSymbolAddress((void**)&xn,   g_xn);
    cudaGetSymbolAddress((void**)&qkvb, g_qkv);
    cudaGetSymbolAddress((void**)&attn, g_attn);
    cudaGetSymbolAddress((void**)&x1,   g_x1);
    cudaGetSymbolAddress((void**)&hb,   g_h);
    cudaGetSymbolAddress((void**)&gb,   g_g);
    cudaGetSymbolAddress((void**)&actb, g_act);

    cudaFuncSetAttribute(attn_kernel, cudaFuncAttributeMaxDynamicSharedMemorySize,
                         ATTN_SMEM_BYTES);

    // 1. LN1
    ln_kernel<<<ROWS, 256>>>(x, ln1w, ln1b, xn);
    // 2. QKV projection (+bias)
    gemm_nt<<<dim3(QKVN / 128, ROWS / 128), 256>>>(xn, wqkv, bqkv, nullptr, qkvb, QKVN, Dc);
    // 3. RoPE
    rope_kernel<<<(ROWS * Hc * (DHc / 2) + 255) / 256, 256>>>(qkvb);
    // 4. Attention
    attn_kernel<<<dim3(Mc / QT, Hc, Bc), 256, ATTN_SMEM_BYTES>>>(qkvb, mask, attn);
    // 5. WO projection + residual(x)
    gemm_nt<<<dim3(Dc / 128, ROWS / 128), 256>>>(attn, wo, nullptr, x, x1, Dc, Dc);
    // 6. LN2
    ln_kernel<<<ROWS, 256>>>(x1, ln2w, ln2b, hb);
    // 7. WI projection
    gemm_nt<<<dim3(WIN / 128, ROWS / 128), 256>>>(hb, wi, nullptr, nullptr, gb, WIN, Dc);
    // 8. GeGLU
    geglu_kernel<<<(ROWS * FFc + 255) / 256, 256>>>(gb, actb);
    // 9. WO_MLP projection + residual(x1) -> out
    gemm_nt<<<dim3(Dc / 128, ROWS / 128), 256>>>(actb, womlp, nullptr, x1, out, Dc, FFc);
}

// round 8
// speedup vs baseline: 1.6580x; 1.6580x over previous
#include <cuda_runtime.h>
#include <math.h>
#include <stdint.h>

// Problem constants
#define Bc   2
#define Mc   2048
#define Dc   1024
#define Hc   16
#define DHc  64
#define FFc  2624
#define ROWS (Bc * Mc)      // 4096
#define QKVN (3 * Dc)       // 3072
#define WIN  (2 * FFc)      // 5248

// ---------------- scratch (device globals; no cudaMalloc allowed) ----------------
__device__ __align__(16) float g_xn  [ROWS * Dc];
__device__ __align__(16) float g_qkv [ROWS * QKVN];
__device__ __align__(16) float g_attn[ROWS * Dc];
__device__ __align__(16) float g_x1  [ROWS * Dc];
__device__ __align__(16) float g_h   [ROWS * Dc];
__device__ __align__(16) float g_g   [(size_t)ROWS * WIN];
__device__ __align__(16) float g_act [(size_t)ROWS * FFc];

// ---------------- NT SGEMM (Round-1 proven): C = A @ B^T (+bias)(+res) ----------------
__global__ void __launch_bounds__(256) gemm_nt(const float* __restrict__ A,
                                               const float* __restrict__ Bw,
                                               const float* __restrict__ bias,
                                               const float* __restrict__ res,
                                               float* __restrict__ C,
                                               int Nd, int Kd) {
    __shared__ __align__(16) float As[16][128];
    __shared__ __align__(16) float Bs[16][128];

    int n0 = blockIdx.x * 128;
    int m0 = blockIdx.y * 128;
    int t  = threadIdx.x;
    int tx = t & 15, ty = t >> 4;

    int lrow = t >> 1;
    int lcol = (t & 1) * 8;

    const float* Ap = A  + (size_t)(m0 + lrow) * Kd + lcol;
    const float* Bp = Bw + (size_t)(n0 + lrow) * Kd + lcol;

    float acc[8][8];
    #pragma unroll
    for (int r = 0; r < 8; r++)
        #pragma unroll
        for (int c = 0; c < 8; c++) acc[r][c] = 0.f;

    for (int k0 = 0; k0 < Kd; k0 += 16) {
        float4 a0 = *reinterpret_cast<const float4*>(Ap + k0);
        float4 a1 = *reinterpret_cast<const float4*>(Ap + k0 + 4);
        float4 b0 = *reinterpret_cast<const float4*>(Bp + k0);
        float4 b1 = *reinterpret_cast<const float4*>(Bp + k0 + 4);
        __syncthreads();
        As[lcol + 0][lrow] = a0.x; As[lcol + 1][lrow] = a0.y;
        As[lcol + 2][lrow] = a0.z; As[lcol + 3][lrow] = a0.w;
        As[lcol + 4][lrow] = a1.x; As[lcol + 5][lrow] = a1.y;
        As[lcol + 6][lrow] = a1.z; As[lcol + 7][lrow] = a1.w;
        Bs[lcol + 0][lrow] = b0.x; Bs[lcol + 1][lrow] = b0.y;
        Bs[lcol + 2][lrow] = b0.z; Bs[lcol + 3][lrow] = b0.w;
        Bs[lcol + 4][lrow] = b1.x; Bs[lcol + 5][lrow] = b1.y;
        Bs[lcol + 6][lrow] = b1.z; Bs[lcol + 7][lrow] = b1.w;
        __syncthreads();

        #pragma unroll
        for (int k = 0; k < 16; k++) {
            float ar[8], br[8];
            *reinterpret_cast<float4*>(ar)     = *reinterpret_cast<float4*>(&As[k][ty * 8]);
            *reinterpret_cast<float4*>(ar + 4) = *reinterpret_cast<float4*>(&As[k][ty * 8 + 4]);
            *reinterpret_cast<float4*>(br)     = *reinterpret_cast<float4*>(&Bs[k][tx * 8]);
            *reinterpret_cast<float4*>(br + 4) = *reinterpret_cast<float4*>(&Bs[k][tx * 8 + 4]);
            #pragma unroll
            for (int r = 0; r < 8; r++)
                #pragma unroll
                for (int c = 0; c < 8; c++) acc[r][c] += ar[r] * br[c];
        }
    }

    float bv[8];
    #pragma unroll
    for (int c = 0; c < 8; c++) bv[c] = bias ? bias[n0 + tx * 8 + c] : 0.f;

    #pragma unroll
    for (int r = 0; r < 8; r++) {
        int gm = m0 + ty * 8 + r;
        float* Cp = C + (size_t)gm * Nd + n0 + tx * 8;
        const float* Rp = res ? (res + (size_t)gm * Nd + n0 + tx * 8) : nullptr;
        #pragma unroll
        for (int c = 0; c < 8; c++) {
            float v = acc[r][c] + bv[c];
            if (res) v += Rp[c];
            Cp[c] = v;
        }
    }
}

// ---------------- LayerNorm ----------------
__global__ void __launch_bounds__(256) ln_kernel(const float* __restrict__ x,
                                                 const float* __restrict__ w,
                                                 const float* __restrict__ b,
                                                 float* __restrict__ out) {
    int row = blockIdx.x;
    int t = threadIdx.x;
    const float4* xr = reinterpret_cast<const float4*>(x + (size_t)row * Dc);
    float4 v = xr[t];
    float s  = v.x + v.y + v.z + v.w;
    float ss = v.x * v.x + v.y * v.y + v.z * v.z + v.w * v.w;

    __shared__ float red0[8], red1[8];
    #pragma unroll
    for (int o = 16; o; o >>= 1) {
        s  += __shfl_xor_sync(0xffffffffu, s,  o);
        ss += __shfl_xor_sync(0xffffffffu, ss, o);
    }
    int wid = t >> 5, lid = t & 31;
    if (lid == 0) { red0[wid] = s; red1[wid] = ss; }
    __syncthreads();
    if (t == 0) {
        float a = 0.f, c = 0.f;
        #pragma unroll
        for (int i = 0; i < 8; i++) { a += red0[i]; c += red1[i]; }
        red0[0] = a; red1[0] = c;
    }
    __syncthreads();
    s = red0[0]; ss = red1[0];
    float mu   = s * (1.0f / Dc);
    float var  = ss * (1.0f / Dc) - mu * mu;
    float rstd = rsqrtf(var + 1e-5f);

    const float4* w4 = reinterpret_cast<const float4*>(w);
    const float4* b4 = reinterpret_cast<const float4*>(b);
    float4 ww = w4[t], bb = b4[t], o4;
    o4.x = (v.x - mu) * rstd * ww.x + bb.x;
    o4.y = (v.y - mu) * rstd * ww.y + bb.y;
    o4.z = (v.z - mu) * rstd * ww.z + bb.z;
    o4.w = (v.w - mu) * rstd * ww.w + bb.w;
    reinterpret_cast<float4*>(out + (size_t)row * Dc)[t] = o4;
}

// ---------------- RoPE ----------------
__global__ void rope_kernel(float* __restrict__ qkv) {
    int idx = blockIdx.x * blockDim.x + threadIdx.x;
    if (idx >= ROWS * Hc * (DHc / 2)) return;
    int j   = idx & 31;
    int h   = (idx >> 5) & (Hc - 1);
    int row = idx >> 9;
    int m   = row & (Mc - 1);

    float inv_freq = powf(10000.0f, -(float)(2 * j) / (float)DHc);
    float freq = (float)m * inv_freq;
    float sn, cs;
    sincosf(freq, &sn, &cs);

    float* qp = qkv + (size_t)row * QKVN + h * DHc;
    float* kp = qp + Dc;
    float q1 = qp[j], q2 = qp[32 + j];
    qp[j]      = q1 * cs - q2 * sn;
    qp[32 + j] = q1 * sn + q2 * cs;
    float k1 = kp[j], k2 = kp[32 + j];
    kp[j]      = k1 * cs - k2 * sn;
    kp[32 + j] = k1 * sn + k2 * cs;
}

// ---------------- Flash attention: 128x128 tiles, 8x8 register blocking ----------------
// 256 threads: ty = t>>4 -> 8-query group; tx = t&15 -> 8-key group (score) / 4-dim group (PV).
// Q,K stored d-major (transposed) in smem; m/l/scale live in registers, reduced via
// half-warp butterfly (the 16 tx lanes of one ty cover all 128 keys).
#define PBS 136            // Pb row stride (floats)
#define F_QT 0             // Qt[64][128]
#define F_KT 8192          // Kt[64][128]
#define F_VS 16384         // Vs[128][64]
#define F_PB 24576         // Pb[128][PBS]
#define F_MSK (F_PB + 128 * PBS)       // 41984, int[128]
#define ATTN_SMEM_BYTES ((F_MSK + 128) * 4)   // 168448

__global__ void __launch_bounds__(256) attn_kernel(const float* __restrict__ qkv,
                                                   const int* __restrict__ mask,
                                                   float* __restrict__ out) {
    extern __shared__ __align__(16) float sh[];
    float* Qt = sh + F_QT;
    float* Kt = sh + F_KT;
    float* Vs = sh + F_VS;
    float* Pb = sh + F_PB;
    int*   msk = reinterpret_cast<int*>(sh + F_MSK);

    const int m0 = blockIdx.x * 128;
    const int h  = blockIdx.y;
    const int b  = blockIdx.z;
    const int t  = threadIdx.x;
    const int ty = t >> 4;
    const int tx = t & 15;

    const float* qbase = qkv + (size_t)(b * Mc + m0) * QKVN + h * DHc;
    const float* kbase = qkv + (size_t)(b * Mc) * QKVN + Dc + h * DHc;
    const float* vbase = kbase + Dc;
    const int*   mbase = mask + b * Mc;

    // load Q transposed (Qt[d][q]), pre-scaled by 1/sqrt(DH)
    {
        const int r   = t & 127;
        const int sg0 = t >> 7;          // 0 or 1
        const float* qrow = qbase + (size_t)r * QKVN;
        #pragma unroll
        for (int sg = sg0; sg < 16; sg += 2) {
            float4 v = *(const float4*)(qrow + sg * 4);
            Qt[(sg * 4 + 0) * 128 + r] = v.x * 0.125f;
            Qt[(sg * 4 + 1) * 128 + r] = v.y * 0.125f;
            Qt[(sg * 4 + 2) * 128 + r] = v.z * 0.125f;
            Qt[(sg * 4 + 3) * 128 + r] = v.w * 0.125f;
        }
    }

    float mreg[8], lreg[8], oacc[8][4];
    #pragma unroll
    for (int i = 0; i < 8; i++) {
        mreg[i] = -1e30f; lreg[i] = 0.f;
        oacc[i][0] = oacc[i][1] = oacc[i][2] = oacc[i][3] = 0.f;
    }

    for (int n0 = 0; n0 < Mc; n0 += 128) {
        __syncthreads();   // previous tile (and Q-load on iter 0) fully consumed
        int myv = 0;
        if (t < 128) { int mv = mbase[n0 + t]; msk[t] = mv; myv = (mv != 0); }
        int any = __syncthreads_or(myv);
        if (!any) continue;            // fully masked tile contributes nothing

        // load K transposed (Kt[d][k]) and V row-major (Vs[k][d])
        {
            const int r   = t & 127;
            const int sg0 = t >> 7;
            const float* krow = kbase + (size_t)(n0 + r) * QKVN;
            #pragma unroll
            for (int sg = sg0; sg < 16; sg += 2) {
                float4 v = *(const float4*)(krow + sg * 4);
                Kt[(sg * 4 + 0) * 128 + r] = v.x;
                Kt[(sg * 4 + 1) * 128 + r] = v.y;
                Kt[(sg * 4 + 2) * 128 + r] = v.z;
                Kt[(sg * 4 + 3) * 128 + r] = v.w;
            }
        }
        #pragma unroll
        for (int idx = t, it = 0; it < 8; idx += 256, it++) {
            int r = idx >> 4, sg = idx & 15;
            *(float4*)&Vs[r * 64 + sg * 4] =
                *(const float4*)(vbase + (size_t)(n0 + r) * QKVN + sg * 4);
        }
        __syncthreads();

        // ---- score: S[8q][8k] = Q-rows . K-rows ----
        float s[8][8];
        #pragma unroll
        for (int i = 0; i < 8; i++)
            #pragma unroll
            for (int j = 0; j < 8; j++) s[i][j] = 0.f;

        #pragma unroll 4
        for (int d = 0; d < 64; d++) {
            float av[8], bv[8];
            *(float4*)(av)     = *(const float4*)&Qt[d * 128 + ty * 8];
            *(float4*)(av + 4) = *(const float4*)&Qt[d * 128 + ty * 8 + 4];
            *(float4*)(bv)     = *(const float4*)&Kt[d * 128 + tx * 8];
            *(float4*)(bv + 4) = *(const float4*)&Kt[d * 128 + tx * 8 + 4];
            #pragma unroll
            for (int i = 0; i < 8; i++)
                #pragma unroll
                for (int j = 0; j < 8; j++) s[i][j] += av[i] * bv[j];
        }

        bool val[8];
        #pragma unroll
        for (int j = 0; j < 8; j++) val[j] = (msk[tx * 8 + j] != 0);

        // ---- online softmax (per-q state in regs; butterfly over 16 tx lanes) ----
        float scr[8];
        #pragma unroll
        for (int i = 0; i < 8; i++) {
            float tm = -1e30f;
            #pragma unroll
            for (int j = 0; j < 8; j++) if (val[j]) tm = fmaxf(tm, s[i][j]);
            tm = fmaxf(tm, __shfl_xor_sync(0xffffffffu, tm, 1));
            tm = fmaxf(tm, __shfl_xor_sync(0xffffffffu, tm, 2));
            tm = fmaxf(tm, __shfl_xor_sync(0xffffffffu, tm, 4));
            tm = fmaxf(tm, __shfl_xor_sync(0xffffffffu, tm, 8));
            float mn = fmaxf(mreg[i], tm);
            float sc = __expf(mreg[i] - mn);
            float rs = 0.f;
            #pragma unroll
            for (int j = 0; j < 8; j++) {
                float p = val[j] ? __expf(s[i][j] - mn) : 0.f;
                s[i][j] = p;
                rs += p;
            }
            rs += __shfl_xor_sync(0xffffffffu, rs, 1);
            rs += __shfl_xor_sync(0xffffffffu, rs, 2);
            rs += __shfl_xor_sync(0xffffffffu, rs, 4);
            rs += __shfl_xor_sync(0xffffffffu, rs, 8);
            lreg[i] = lreg[i] * sc + rs;
            mreg[i] = mn;
            scr[i]  = sc;
            *(float4*)&Pb[(ty * 8 + i) * PBS + tx * 8]     =
                make_float4(s[i][0], s[i][1], s[i][2], s[i][3]);
            *(float4*)&Pb[(ty * 8 + i) * PBS + tx * 8 + 4] =
                make_float4(s[i][4], s[i][5], s[i][6], s[i][7]);
        }
        __syncthreads();

        // ---- PV: O[8q][4d], d = tx*4..+3 ----
        #pragma unroll
        for (int i = 0; i < 8; i++) {
            oacc[i][0] *= scr[i]; oacc[i][1] *= scr[i];
            oacc[i][2] *= scr[i]; oacc[i][3] *= scr[i];
        }
        #pragma unroll 2
        for (int kc = 0; kc < 128; kc += 4) {
            float4 v0 = *(const float4*)&Vs[(kc + 0) * 64 + tx * 4];
            float4 v1 = *(const float4*)&Vs[(kc + 1) * 64 + tx * 4];
            float4 v2 = *(const float4*)&Vs[(kc + 2) * 64 + tx * 4];
            float4 v3 = *(const float4*)&Vs[(kc + 3) * 64 + tx * 4];
            #pragma unroll
            for (int i = 0; i < 8; i++) {
                float4 p4 = *(const float4*)&Pb[(ty * 8 + i) * PBS + kc];
                oacc[i][0] += p4.x * v0.x; oacc[i][1] += p4.x * v0.y;
                oacc[i][2] += p4.x * v0.z; oacc[i][3] += p4.x * v0.w;
                oacc[i][0] += p4.y * v1.x; oacc[i][1] += p4.y * v1.y;
                oacc[i][2] += p4.y * v1.z; oacc[i][3] += p4.y * v1.w;
                oacc[i][0] += p4.z * v2.x; oacc[i][1] += p4.z * v2.y;
                oacc[i][2] += p4.z * v2.z; oacc[i][3] += p4.z * v2.w;
                oacc[i][0] += p4.w * v3.x; oacc[i][1] += p4.w * v3.y;
                oacc[i][2] += p4.w * v3.z; oacc[i][3] += p4.w * v3.w;
            }
        }
    }

    // final normalize + store
    #pragma unroll
    for (int i = 0; i < 8; i++) {
        float inv = 1.0f / lreg[i];
        float* op = out + (size_t)(b * Mc + m0 + ty * 8 + i) * Dc + h * DHc + tx * 4;
        *(float4*)op = make_float4(oacc[i][0] * inv, oacc[i][1] * inv,
                                   oacc[i][2] * inv, oacc[i][3] * inv);
    }
}

// ---------------- GeGLU (exact gelu * gate) ----------------
__global__ void geglu_kernel(const float* __restrict__ g, float* __restrict__ act) {
    int idx = blockIdx.x * blockDim.x + threadIdx.x;
    if (idx >= ROWS * FFc) return;
    int r = idx / FFc;
    int j = idx - r * FFc;
    float x    = g[(size_t)r * WIN + j];
    float gate = g[(size_t)r * WIN + FFc + j];
    float ge = 0.5f * x * (1.0f + erff(x * 0.7071067811865476f));
    act[idx] = ge * gate;
}

// ---------------- launch ----------------
extern "C" void kernel_launch(void* const* d_in, const int* in_sizes, int n_in,
                              void* d_out, int out_size) {
    const float* x     = (const float*)d_in[0];
    const int*   mask  = (const int*)  d_in[1];
    const float* ln1w  = (const float*)d_in[2];
    const float* ln1b  = (const float*)d_in[3];
    const float* wqkv  = (const float*)d_in[4];
    const float* bqkv  = (const float*)d_in[5];
    const float* wo    = (const float*)d_in[6];
    const float* ln2w  = (const float*)d_in[7];
    const float* ln2b  = (const float*)d_in[8];
    const float* wi    = (const float*)d_in[9];
    const float* womlp = (const float*)d_in[10];
    float* out = (float*)d_out;

    float *xn, *qkvb, *attn, *x1, *hb, *gb, *actb;
    cudaGetSymbolAddress((void**)&xn,   g_xn);
    cudaGetSymbolAddress((void**)&qkvb, g_qkv);
    cudaGetSymbolAddress((void**)&attn, g_attn);
    cudaGetSymbolAddress((void**)&x1,   g_x1);
    cudaGetSymbolAddress((void**)&hb,   g_h);
    cudaGetSymbolAddress((void**)&gb,   g_g);
    cudaGetSymbolAddress((void**)&actb, g_act);

    cudaFuncSetAttribute(attn_kernel, cudaFuncAttributeMaxDynamicSharedMemorySize,
                         ATTN_SMEM_BYTES);

    // 1. LN1
    ln_kernel<<<ROWS, 256>>>(x, ln1w, ln1b, xn);
    // 2. QKV projection (+bias)
    gemm_nt<<<dim3(QKVN / 128, ROWS / 128), 256>>>(xn, wqkv, bqkv, nullptr, qkvb, QKVN, Dc);
    // 3. RoPE
    rope_kernel<<<(ROWS * Hc * (DHc / 2) + 255) / 256, 256>>>(qkvb);
    // 4. Attention
    attn_kernel<<<dim3(Mc / 128, Hc, Bc), 256, ATTN_SMEM_BYTES>>>(qkvb, mask, attn);
    // 5. WO projection + residual(x)
    gemm_nt<<<dim3(Dc / 128, ROWS / 128), 256>>>(attn, wo, nullptr, x, x1, Dc, Dc);
    // 6. LN2
    ln_kernel<<<ROWS, 256>>>(x1, ln2w, ln2b, hb);
    // 7. WI projection
    gemm_nt<<<dim3(WIN / 128, ROWS / 128), 256>>>(hb, wi, nullptr, nullptr, gb, WIN, Dc);
    // 8. GeGLU
    geglu_kernel<<<(ROWS * FFc + 255) / 256, 256>>>(gb, actb);
    // 9. WO_MLP projection + residual(x1) -> out
    gemm_nt<<<dim3(Dc / 128, ROWS / 128), 256>>>(actb, womlp, nullptr, x1, out, Dc, FFc);
}

// round 9
// speedup vs baseline: 2.0000x; 1.2062x over previous
#include <cuda_runtime.h>
#include <cuda_fp16.h>
#include <math.h>
#include <stdint.h>

// Problem constants
#define Bc   2
#define Mc   2048
#define Dc   1024
#define Hc   16
#define DHc  64
#define FFc  2624
#define ROWS (Bc * Mc)      // 4096
#define QKVN (3 * Dc)       // 3072
#define WIN  (2 * FFc)      // 5248

// ---------------- scratch (device globals; no cudaMalloc allowed) ----------------
__device__ __align__(16) float g_xn  [ROWS * Dc];
__device__ __align__(16) float g_qkv [ROWS * QKVN];
__device__ __align__(16) float g_attn[ROWS * Dc];
__device__ __align__(16) float g_x1  [ROWS * Dc];
__device__ __align__(16) float g_h   [ROWS * Dc];
__device__ __align__(16) float g_g   [(size_t)ROWS * WIN];
__device__ __align__(16) float g_act [(size_t)ROWS * FFc];

// ---------------- fp16 mma helper: m16n8k16, fp16 inputs, fp32 accumulate ----------------
__device__ __forceinline__ void mma_f16(float* c, const uint32_t* a, const uint32_t* b) {
    asm volatile(
        "mma.sync.aligned.m16n8k16.row.col.f32.f16.f16.f32 "
        "{%0,%1,%2,%3}, {%4,%5,%6,%7}, {%8,%9}, {%0,%1,%2,%3};"
        : "+f"(c[0]), "+f"(c[1]), "+f"(c[2]), "+f"(c[3])
        : "r"(a[0]), "r"(a[1]), "r"(a[2]), "r"(a[3]), "r"(b[0]), "r"(b[1]));
}

// ======== fp16 tensor NT GEMM: C[M,Nd] = A[M,Kd] @ B[Nd,Kd]^T (+bias)(+res) ========
// BM=BN=128, BK=32, 256 threads (8 warps 2x4), warp tile 64x32 = 4x4 m16n8k16 (2 k-steps).
#define AS_STR 40   // half units per row (32 + 8 skew); 20 words -> conflict-free frags
__global__ void __launch_bounds__(256) gemm_h(const float* __restrict__ A,
                                              const float* __restrict__ Bw,
                                              const float* __restrict__ bias,
                                              const float* __restrict__ res,
                                              float* __restrict__ C,
                                              int Nd, int Kd) {
    __shared__ __align__(16) __half As[128 * AS_STR];
    __shared__ __align__(16) __half Bs[128 * AS_STR];

    const int t    = threadIdx.x;
    const int lane = t & 31;
    const int warp = t >> 5;
    const int wm   = (warp & 1) * 64;
    const int wn   = (warp >> 1) * 32;
    const int gid  = lane >> 2;
    const int tig  = lane & 3;

    const int m0 = blockIdx.y * 128;
    const int n0 = blockIdx.x * 128;

    const int lrow = t >> 1;
    const int lcol = (t & 1) * 16;
    const float* Ap = A  + (size_t)(m0 + lrow) * Kd + lcol;
    const float* Bp = Bw + (size_t)(n0 + lrow) * Kd + lcol;

    float acc[4][4][4];
    #pragma unroll
    for (int mt = 0; mt < 4; mt++)
        #pragma unroll
        for (int nt = 0; nt < 4; nt++)
            #pragma unroll
            for (int c = 0; c < 4; c++) acc[mt][nt][c] = 0.f;

    float4 pa[4], pb[4];
    #pragma unroll
    for (int j = 0; j < 4; j++) {
        pa[j] = *(const float4*)(Ap + 4 * j);
        pb[j] = *(const float4*)(Bp + 4 * j);
    }

    const int nch = Kd >> 5;
    for (int i = 0; i < nch; i++) {
        __syncthreads();
        #pragma unroll
        for (int j = 0; j < 4; j++) {
            *(half2*)&As[lrow * AS_STR + lcol + 4 * j]     =
                __float22half2_rn(make_float2(pa[j].x, pa[j].y));
            *(half2*)&As[lrow * AS_STR + lcol + 4 * j + 2] =
                __float22half2_rn(make_float2(pa[j].z, pa[j].w));
            *(half2*)&Bs[lrow * AS_STR + lcol + 4 * j]     =
                __float22half2_rn(make_float2(pb[j].x, pb[j].y));
            *(half2*)&Bs[lrow * AS_STR + lcol + 4 * j + 2] =
                __float22half2_rn(make_float2(pb[j].z, pb[j].w));
        }
        __syncthreads();

        if (i + 1 < nch) {
            const float* An = Ap + (i + 1) * 32;
            const float* Bn = Bp + (i + 1) * 32;
            #pragma unroll
            for (int j = 0; j < 4; j++) {
                pa[j] = *(const float4*)(An + 4 * j);
                pb[j] = *(const float4*)(Bn + 4 * j);
            }
        }

        #pragma unroll
        for (int ks = 0; ks < 2; ks++) {
            const int koff = ks * 16;
            uint32_t af[4][4], bf[4][2];
            #pragma unroll
            for (int mt = 0; mt < 4; mt++) {
                const int r = wm + mt * 16 + gid;
                af[mt][0] = *(const uint32_t*)&As[r * AS_STR + koff + 2 * tig];
                af[mt][1] = *(const uint32_t*)&As[(r + 8) * AS_STR + koff + 2 * tig];
                af[mt][2] = *(const uint32_t*)&As[r * AS_STR + koff + 2 * tig + 8];
                af[mt][3] = *(const uint32_t*)&As[(r + 8) * AS_STR + koff + 2 * tig + 8];
            }
            #pragma unroll
            for (int nt = 0; nt < 4; nt++) {
                const int cI = wn + nt * 8 + gid;
                bf[nt][0] = *(const uint32_t*)&Bs[cI * AS_STR + koff + 2 * tig];
                bf[nt][1] = *(const uint32_t*)&Bs[cI * AS_STR + koff + 2 * tig + 8];
            }
            #pragma unroll
            for (int mt = 0; mt < 4; mt++)
                #pragma unroll
                for (int nt = 0; nt < 4; nt++)
                    mma_f16(acc[mt][nt], af[mt], bf[nt]);
        }
    }

    // epilogue: bias + residual, float2 stores
    #pragma unroll
    for (int mt = 0; mt < 4; mt++) {
        #pragma unroll
        for (int half = 0; half < 2; half++) {
            const int gm = m0 + wm + mt * 16 + gid + half * 8;
            float* Cp = C + (size_t)gm * Nd + n0 + wn;
            const float* Rp = res ? res + (size_t)gm * Nd + n0 + wn : nullptr;
            #pragma unroll
            for (int nt = 0; nt < 4; nt++) {
                const int cc = nt * 8 + 2 * tig;
                float v0 = acc[mt][nt][half * 2 + 0];
                float v1 = acc[mt][nt][half * 2 + 1];
                if (bias) {
                    v0 += bias[n0 + wn + cc];
                    v1 += bias[n0 + wn + cc + 1];
                }
                if (Rp) {
                    v0 += Rp[cc];
                    v1 += Rp[cc + 1];
                }
                *(float2*)(Cp + cc) = make_float2(v0, v1);
            }
        }
    }
}

// ---------------- LayerNorm ----------------
__global__ void __launch_bounds__(256) ln_kernel(const float* __restrict__ x,
                                                 const float* __restrict__ w,
                                                 const float* __restrict__ b,
                                                 float* __restrict__ out) {
    int row = blockIdx.x;
    int t = threadIdx.x;
    const float4* xr = reinterpret_cast<const float4*>(x + (size_t)row * Dc);
    float4 v = xr[t];
    float s  = v.x + v.y + v.z + v.w;
    float ss = v.x * v.x + v.y * v.y + v.z * v.z + v.w * v.w;

    __shared__ float red0[8], red1[8];
    #pragma unroll
    for (int o = 16; o; o >>= 1) {
        s  += __shfl_xor_sync(0xffffffffu, s,  o);
        ss += __shfl_xor_sync(0xffffffffu, ss, o);
    }
    int wid = t >> 5, lid = t & 31;
    if (lid == 0) { red0[wid] = s; red1[wid] = ss; }
    __syncthreads();
    if (t == 0) {
        float a = 0.f, c = 0.f;
        #pragma unroll
        for (int i = 0; i < 8; i++) { a += red0[i]; c += red1[i]; }
        red0[0] = a; red1[0] = c;
    }
    __syncthreads();
    s = red0[0]; ss = red1[0];
    float mu   = s * (1.0f / Dc);
    float var  = ss * (1.0f / Dc) - mu * mu;
    float rstd = rsqrtf(var + 1e-5f);

    const float4* w4 = reinterpret_cast<const float4*>(w);
    const float4* b4 = reinterpret_cast<const float4*>(b);
    float4 ww = w4[t], bb = b4[t], o4;
    o4.x = (v.x - mu) * rstd * ww.x + bb.x;
    o4.y = (v.y - mu) * rstd * ww.y + bb.y;
    o4.z = (v.z - mu) * rstd * ww.z + bb.z;
    o4.w = (v.w - mu) * rstd * ww.w + bb.w;
    reinterpret_cast<float4*>(out + (size_t)row * Dc)[t] = o4;
}

// ---------------- RoPE ----------------
__global__ void rope_kernel(float* __restrict__ qkv) {
    int idx = blockIdx.x * blockDim.x + threadIdx.x;
    if (idx >= ROWS * Hc * (DHc / 2)) return;
    int j   = idx & 31;
    int h   = (idx >> 5) & (Hc - 1);
    int row = idx >> 9;
    int m   = row & (Mc - 1);

    float inv_freq = powf(10000.0f, -(float)(2 * j) / (float)DHc);
    float freq = (float)m * inv_freq;
    float sn, cs;
    sincosf(freq, &sn, &cs);

    float* qp = qkv + (size_t)row * QKVN + h * DHc;
    float* kp = qp + Dc;
    float q1 = qp[j], q2 = qp[32 + j];
    qp[j]      = q1 * cs - q2 * sn;
    qp[32 + j] = q1 * sn + q2 * cs;
    float k1 = kp[j], k2 = kp[32 + j];
    kp[j]      = k1 * cs - k2 * sn;
    kp[32 + j] = k1 * sn + k2 * cs;
}

// ---------------- Flash attention: 128x128 tiles, 8x8 register blocking ----------------
#define PBS 136
#define F_QT 0
#define F_KT 8192
#define F_VS 16384
#define F_PB 24576
#define F_MSK (F_PB + 128 * PBS)
#define ATTN_SMEM_BYTES ((F_MSK + 128) * 4)

__global__ void __launch_bounds__(256) attn_kernel(const float* __restrict__ qkv,
                                                   const int* __restrict__ mask,
                                                   float* __restrict__ out) {
    extern __shared__ __align__(16) float sh[];
    float* Qt = sh + F_QT;
    float* Kt = sh + F_KT;
    float* Vs = sh + F_VS;
    float* Pb = sh + F_PB;
    int*   msk = reinterpret_cast<int*>(sh + F_MSK);

    const int m0 = blockIdx.x * 128;
    const int h  = blockIdx.y;
    const int b  = blockIdx.z;
    const int t  = threadIdx.x;
    const int ty = t >> 4;
    const int tx = t & 15;

    const float* qbase = qkv + (size_t)(b * Mc + m0) * QKVN + h * DHc;
    const float* kbase = qkv + (size_t)(b * Mc) * QKVN + Dc + h * DHc;
    const float* vbase = kbase + Dc;
    const int*   mbase = mask + b * Mc;

    {
        const int r   = t & 127;
        const int sg0 = t >> 7;
        const float* qrow = qbase + (size_t)r * QKVN;
        #pragma unroll
        for (int sg = sg0; sg < 16; sg += 2) {
            float4 v = *(const float4*)(qrow + sg * 4);
            Qt[(sg * 4 + 0) * 128 + r] = v.x * 0.125f;
            Qt[(sg * 4 + 1) * 128 + r] = v.y * 0.125f;
            Qt[(sg * 4 + 2) * 128 + r] = v.z * 0.125f;
            Qt[(sg * 4 + 3) * 128 + r] = v.w * 0.125f;
        }
    }

    float mreg[8], lreg[8], oacc[8][4];
    #pragma unroll
    for (int i = 0; i < 8; i++) {
        mreg[i] = -1e30f; lreg[i] = 0.f;
        oacc[i][0] = oacc[i][1] = oacc[i][2] = oacc[i][3] = 0.f;
    }

    for (int n0 = 0; n0 < Mc; n0 += 128) {
        __syncthreads();
        int myv = 0;
        if (t < 128) { int mv = mbase[n0 + t]; msk[t] = mv; myv = (mv != 0); }
        int any = __syncthreads_or(myv);
        if (!any) continue;

        {
            const int r   = t & 127;
            const int sg0 = t >> 7;
            const float* krow = kbase + (size_t)(n0 + r) * QKVN;
            #pragma unroll
            for (int sg = sg0; sg < 16; sg += 2) {
                float4 v = *(const float4*)(krow + sg * 4);
                Kt[(sg * 4 + 0) * 128 + r] = v.x;
                Kt[(sg * 4 + 1) * 128 + r] = v.y;
                Kt[(sg * 4 + 2) * 128 + r] = v.z;
                Kt[(sg * 4 + 3) * 128 + r] = v.w;
            }
        }
        #pragma unroll
        for (int idx = t, it = 0; it < 8; idx += 256, it++) {
            int r = idx >> 4, sg = idx & 15;
            *(float4*)&Vs[r * 64 + sg * 4] =
                *(const float4*)(vbase + (size_t)(n0 + r) * QKVN + sg * 4);
        }
        __syncthreads();

        float s[8][8];
        #pragma unroll
        for (int i = 0; i < 8; i++)
            #pragma unroll
            for (int j = 0; j < 8; j++) s[i][j] = 0.f;

        #pragma unroll 4
        for (int d = 0; d < 64; d++) {
            float av[8], bv[8];
            *(float4*)(av)     = *(const float4*)&Qt[d * 128 + ty * 8];
            *(float4*)(av + 4) = *(const float4*)&Qt[d * 128 + ty * 8 + 4];
            *(float4*)(bv)     = *(const float4*)&Kt[d * 128 + tx * 8];
            *(float4*)(bv + 4) = *(const float4*)&Kt[d * 128 + tx * 8 + 4];
            #pragma unroll
            for (int i = 0; i < 8; i++)
                #pragma unroll
                for (int j = 0; j < 8; j++) s[i][j] += av[i] * bv[j];
        }

        bool val[8];
        #pragma unroll
        for (int j = 0; j < 8; j++) val[j] = (msk[tx * 8 + j] != 0);

        float scr[8];
        #pragma unroll
        for (int i = 0; i < 8; i++) {
            float tm = -1e30f;
            #pragma unroll
            for (int j = 0; j < 8; j++) if (val[j]) tm = fmaxf(tm, s[i][j]);
            tm = fmaxf(tm, __shfl_xor_sync(0xffffffffu, tm, 1));
            tm = fmaxf(tm, __shfl_xor_sync(0xffffffffu, tm, 2));
            tm = fmaxf(tm, __shfl_xor_sync(0xffffffffu, tm, 4));
            tm = fmaxf(tm, __shfl_xor_sync(0xffffffffu, tm, 8));
            float mn = fmaxf(mreg[i], tm);
            float sc = __expf(mreg[i] - mn);
            float rs = 0.f;
            #pragma unroll
            for (int j = 0; j < 8; j++) {
                float p = val[j] ? __expf(s[i][j] - mn) : 0.f;
                s[i][j] = p;
                rs += p;
            }
            rs += __shfl_xor_sync(0xffffffffu, rs, 1);
            rs += __shfl_xor_sync(0xffffffffu, rs, 2);
            rs += __shfl_xor_sync(0xffffffffu, rs, 4);
            rs += __shfl_xor_sync(0xffffffffu, rs, 8);
            lreg[i] = lreg[i] * sc + rs;
            mreg[i] = mn;
            scr[i]  = sc;
            *(float4*)&Pb[(ty * 8 + i) * PBS + tx * 8]     =
                make_float4(s[i][0], s[i][1], s[i][2], s[i][3]);
            *(float4*)&Pb[(ty * 8 + i) * PBS + tx * 8 + 4] =
                make_float4(s[i][4], s[i][5], s[i][6], s[i][7]);
        }
        __syncthreads();

        #pragma unroll
        for (int i = 0; i < 8; i++) {
            oacc[i][0] *= scr[i]; oacc[i][1] *= scr[i];
            oacc[i][2] *= scr[i]; oacc[i][3] *= scr[i];
        }
        #pragma unroll 2
        for (int kc = 0; kc < 128; kc += 4) {
            float4 v0 = *(const float4*)&Vs[(kc + 0) * 64 + tx * 4];
            float4 v1 = *(const float4*)&Vs[(kc + 1) * 64 + tx * 4];
            float4 v2 = *(const float4*)&Vs[(kc + 2) * 64 + tx * 4];
            float4 v3 = *(const float4*)&Vs[(kc + 3) * 64 + tx * 4];
            #pragma unroll
            for (int i = 0; i < 8; i++) {
                float4 p4 = *(const float4*)&Pb[(ty * 8 + i) * PBS + kc];
                oacc[i][0] += p4.x * v0.x; oacc[i][1] += p4.x * v0.y;
                oacc[i][2] += p4.x * v0.z; oacc[i][3] += p4.x * v0.w;
                oacc[i][0] += p4.y * v1.x; oacc[i][1] += p4.y * v1.y;
                oacc[i][2] += p4.y * v1.z; oacc[i][3] += p4.y * v1.w;
                oacc[i][0] += p4.z * v2.x; oacc[i][1] += p4.z * v2.y;
                oacc[i][2] += p4.z * v2.z; oacc[i][3] += p4.z * v2.w;
                oacc[i][0] += p4.w * v3.x; oacc[i][1] += p4.w * v3.y;
                oacc[i][2] += p4.w * v3.z; oacc[i][3] += p4.w * v3.w;
            }
        }
    }

    #pragma unroll
    for (int i = 0; i < 8; i++) {
        float inv = 1.0f / lreg[i];
        float* op = out + (size_t)(b * Mc + m0 + ty * 8 + i) * Dc + h * DHc + tx * 4;
        *(float4*)op = make_float4(oacc[i][0] * inv, oacc[i][1] * inv,
                                   oacc[i][2] * inv, oacc[i][3] * inv);
    }
}

// ---------------- GeGLU (exact gelu * gate) ----------------
__global__ void geglu_kernel(const float* __restrict__ g, float* __restrict__ act) {
    int idx = blockIdx.x * blockDim.x + threadIdx.x;
    if (idx >= ROWS * FFc) return;
    int r = idx / FFc;
    int j = idx - r * FFc;
    float x    = g[(size_t)r * WIN + j];
    float gate = g[(size_t)r * WIN + FFc + j];
    float ge = 0.5f * x * (1.0f + erff(x * 0.7071067811865476f));
    act[idx] = ge * gate;
}

// ---------------- launch ----------------
extern "C" void kernel_launch(void* const* d_in, const int* in_sizes, int n_in,
                              void* d_out, int out_size) {
    const float* x     = (const float*)d_in[0];
    const int*   mask  = (const int*)  d_in[1];
    const float* ln1w  = (const float*)d_in[2];
    const float* ln1b  = (const float*)d_in[3];
    const float* wqkv  = (const float*)d_in[4];
    const float* bqkv  = (const float*)d_in[5];
    const float* wo    = (const float*)d_in[6];
    const float* ln2w  = (const float*)d_in[7];
    const float* ln2b  = (const float*)d_in[8];
    const float* wi    = (const float*)d_in[9];
    const float* womlp = (const float*)d_in[10];
    float* out = (float*)d_out;

    float *xn, *qkvb, *attn, *x1, *hb, *gb, *actb;
    cudaGetSymbolAddress((void**)&xn,   g_xn);
    cudaGetSymbolAddress((void**)&qkvb, g_qkv);
    cudaGetSymbolAddress((void**)&attn, g_attn);
    cudaGetSymbolAddress((void**)&x1,   g_x1);
    cudaGetSymbolAddress((void**)&hb,   g_h);
    cudaGetSymbolAddress((void**)&gb,   g_g);
    cudaGetSymbolAddress((void**)&actb, g_act);

    cudaFuncSetAttribute(attn_kernel, cudaFuncAttributeMaxDynamicSharedMemorySize,
                         ATTN_SMEM_BYTES);

    // 1. LN1
    ln_kernel<<<ROWS, 256>>>(x, ln1w, ln1b, xn);
    // 2. QKV projection (+bias)
    gemm_h<<<dim3(QKVN / 128, ROWS / 128), 256>>>(xn, wqkv, bqkv, nullptr, qkvb, QKVN, Dc);
    // 3. RoPE
    rope_kernel<<<(ROWS * Hc * (DHc / 2) + 255) / 256, 256>>>(qkvb);
    // 4. Attention
    attn_kernel<<<dim3(Mc / 128, Hc, Bc), 256, ATTN_SMEM_BYTES>>>(qkvb, mask, attn);
    // 5. WO projection + residual(x)
    gemm_h<<<dim3(Dc / 128, ROWS / 128), 256>>>(attn, wo, nullptr, x, x1, Dc, Dc);
    // 6. LN2
    ln_kernel<<<ROWS, 256>>>(x1, ln2w, ln2b, hb);
    // 7. WI projection
    gemm_h<<<dim3(WIN / 128, ROWS / 128), 256>>>(hb, wi, nullptr, nullptr, gb, WIN, Dc);
    // 8. GeGLU
    geglu_kernel<<<(ROWS * FFc + 255) / 256, 256>>>(gb, actb);
    // 9. WO_MLP projection + residual(x1) -> out
    gemm_h<<<dim3(Dc / 128, ROWS / 128), 256>>>(actb, womlp, nullptr, x1, out, Dc, FFc);
}

// round 14
// speedup vs baseline: 3.8960x; 1.9480x over previous
#include <cuda_runtime.h>
#include <cuda_fp16.h>
#include <math.h>
#include <stdint.h>

// Problem constants
#define Bc   2
#define Mc   2048
#define Dc   1024
#define Hc   16
#define DHc  64
#define FFc  2624
#define ROWS (Bc * Mc)      // 4096
#define QKVN (3 * Dc)       // 3072
#define WIN  (2 * FFc)      // 5248

// ---------------- scratch (device globals; no cudaMalloc allowed) ----------------
__device__ __align__(16) float  g_qkv [ROWS * QKVN];            // fp32 (rope + attn)
__device__ __align__(16) float  g_x1  [ROWS * Dc];              // fp32 residual
__device__ __align__(16) float  g_g   [(size_t)ROWS * WIN];     // fp32 WI output
__device__ __align__(16) __half h_xn  [ROWS * Dc];
__device__ __align__(16) __half h_attn[ROWS * Dc];
__device__ __align__(16) __half h_h   [ROWS * Dc];
__device__ __align__(16) __half h_act [(size_t)ROWS * FFc];
__device__ __align__(16) __half hw_qkv[QKVN * Dc];
__device__ __align__(16) __half hw_o  [Dc * Dc];
__device__ __align__(16) __half hw_i  [(size_t)WIN * Dc];
__device__ __align__(16) __half hw_om [Dc * FFc];

// ---------------- asm helpers ----------------
__device__ __forceinline__ void mma_f16(float* c, const uint32_t* a, const uint32_t* b) {
    asm volatile(
        "mma.sync.aligned.m16n8k16.row.col.f32.f16.f16.f32 "
        "{%0,%1,%2,%3}, {%4,%5,%6,%7}, {%8,%9}, {%0,%1,%2,%3};"
        : "+f"(c[0]), "+f"(c[1]), "+f"(c[2]), "+f"(c[3])
        : "r"(a[0]), "r"(a[1]), "r"(a[2]), "r"(a[3]), "r"(b[0]), "r"(b[1]));
}
#define LDSM_X4(d0,d1,d2,d3,addr) \
    asm volatile("ldmatrix.sync.aligned.m8n8.x4.shared.b16 {%0,%1,%2,%3}, [%4];" \
        : "=r"(d0),"=r"(d1),"=r"(d2),"=r"(d3) : "r"(addr))
#define LDSM_X2(d0,d1,addr) \
    asm volatile("ldmatrix.sync.aligned.m8n8.x2.shared.b16 {%0,%1}, [%2];" \
        : "=r"(d0),"=r"(d1) : "r"(addr))
#define CP_ASYNC16(smem,gptr) \
    asm volatile("cp.async.cg.shared.global [%0], [%1], 16;" :: "r"(smem), "l"(gptr))
#define CP_COMMIT() asm volatile("cp.async.commit_group;")
#define CP_WAIT1()  asm volatile("cp.async.wait_group 1;")
#define CP_WAIT0()  asm volatile("cp.async.wait_group 0;")

// ======== fp16 tensor NT GEMM: C[M,Nd] = A[M,Kd] @ B[Nd,Kd]^T (+bias)(+res) ========
// BM=BN=128, BK=32, 256 threads (8 warps 2x4), warp tile 64x32 = 4x4 m16n8k16.
// cp.async double buffer + ldmatrix fragments; HSTR=40 halves -> conflict-free.
#define HSTR 40
__global__ void __launch_bounds__(256, 2) gemm_h2(const __half* __restrict__ A,
                                                  const __half* __restrict__ Bw,
                                                  const float* __restrict__ bias,
                                                  const float* __restrict__ res,
                                                  float* __restrict__ C,
                                                  int Nd, int Kd) {
    __shared__ __align__(16) __half As[2][128 * HSTR];
    __shared__ __align__(16) __half Bs[2][128 * HSTR];

    const int t    = threadIdx.x;
    const int lane = t & 31;
    const int warp = t >> 5;
    const int wm   = (warp & 1) * 64;
    const int wn   = (warp >> 1) * 32;

    const int m0 = blockIdx.y * 128;
    const int n0 = blockIdx.x * 128;

    // loader mapping: 2 threads/row, 16 halves (32B) each -> two 16B cp.async
    const int lrow = t >> 1;
    const int lcol = (t & 1) * 16;
    const __half* Ap = A  + (size_t)(m0 + lrow) * Kd + lcol;
    const __half* Bp = Bw + (size_t)(n0 + lrow) * Kd + lcol;

    uint32_t sA[2], sB[2];
    sA[0] = (uint32_t)__cvta_generic_to_shared(&As[0][0]);
    sA[1] = (uint32_t)__cvta_generic_to_shared(&As[1][0]);
    sB[0] = (uint32_t)__cvta_generic_to_shared(&Bs[0][0]);
    sB[1] = (uint32_t)__cvta_generic_to_shared(&Bs[1][0]);
    const uint32_t stoff = (uint32_t)(lrow * HSTR + lcol) * 2;

    // ldmatrix source addresses (byte offsets within one buffer)
    const int arow = wm + (lane & 15);
    const int acol = ((lane >> 4) & 1) * 8;
    const int brow = wn + (lane & 7);
    const int bcol = ((lane >> 3) & 1) * 8;

    float acc[4][4][4];
    #pragma unroll
    for (int mt = 0; mt < 4; mt++)
        #pragma unroll
        for (int nt = 0; nt < 4; nt++)
            #pragma unroll
            for (int c = 0; c < 4; c++) acc[mt][nt][c] = 0.f;

    const int nch = Kd >> 5;
    // prologue: chunk 0 -> buf 0
    CP_ASYNC16(sA[0] + stoff,      Ap);
    CP_ASYNC16(sA[0] + stoff + 16, Ap + 8);
    CP_ASYNC16(sB[0] + stoff,      Bp);
    CP_ASYNC16(sB[0] + stoff + 16, Bp + 8);
    CP_COMMIT();

    for (int i = 0; i < nch; i++) {
        const int b = i & 1;
        if (i + 1 < nch) {
            const int nb = (i + 1) & 1;
            const __half* An = Ap + (i + 1) * 32;
            const __half* Bn = Bp + (i + 1) * 32;
            CP_ASYNC16(sA[nb] + stoff,      An);
            CP_ASYNC16(sA[nb] + stoff + 16, An + 8);
            CP_ASYNC16(sB[nb] + stoff,      Bn);
            CP_ASYNC16(sB[nb] + stoff + 16, Bn + 8);
            CP_COMMIT();
            CP_WAIT1();
        } else {
            CP_WAIT0();
        }
        __syncthreads();

        #pragma unroll
        for (int ks = 0; ks < 2; ks++) {
            const int koff = ks * 16;
            uint32_t af[4][4], bf[4][2];
            #pragma unroll
            for (int mt = 0; mt < 4; mt++) {
                uint32_t ad = sA[b] + (uint32_t)(((arow + mt * 16) * HSTR) + koff + acol) * 2;
                LDSM_X4(af[mt][0], af[mt][1], af[mt][2], af[mt][3], ad);
            }
            #pragma unroll
            for (int nt = 0; nt < 4; nt++) {
                uint32_t bd = sB[b] + (uint32_t)(((brow + nt * 8) * HSTR) + koff + bcol) * 2;
                LDSM_X2(bf[nt][0], bf[nt][1], bd);
            }
            #pragma unroll
            for (int mt = 0; mt < 4; mt++)
                #pragma unroll
                for (int nt = 0; nt < 4; nt++)
                    mma_f16(acc[mt][nt], af[mt], bf[nt]);
        }
        __syncthreads();   // compute done before this buffer is refilled
    }

    // epilogue
    const int gid = lane >> 2;
    const int tig = lane & 3;
    #pragma unroll
    for (int mt = 0; mt < 4; mt++) {
        #pragma unroll
        for (int hf = 0; hf < 2; hf++) {
            const int gm = m0 + wm + mt * 16 + gid + hf * 8;
            float* Cp = C + (size_t)gm * Nd + n0 + wn;
            const float* Rp = res ? res + (size_t)gm * Nd + n0 + wn : nullptr;
            #pragma unroll
            for (int nt = 0; nt < 4; nt++) {
                const int cc = nt * 8 + 2 * tig;
                float v0 = acc[mt][nt][hf * 2 + 0];
                float v1 = acc[mt][nt][hf * 2 + 1];
                if (bias) {
                    v0 += bias[n0 + wn + cc];
                    v1 += bias[n0 + wn + cc + 1];
                }
                if (Rp) {
                    v0 += Rp[cc];
                    v1 += Rp[cc + 1];
                }
                *(float2*)(Cp + cc) = make_float2(v0, v1);
            }
        }
    }
}

// ---------------- weight convert fp32 -> fp16 ----------------
__global__ void wcvt(const float* __restrict__ w, __half* __restrict__ o, int n4) {
    int idx = blockIdx.x * blockDim.x + threadIdx.x;
    if (idx >= n4) return;
    float4 v = ((const float4*)w)[idx];
    half2 a = __float22half2_rn(make_float2(v.x, v.y));
    half2 b = __float22half2_rn(make_float2(v.z, v.w));
    ((uint2*)o)[idx] = make_uint2(*(uint32_t*)&a, *(uint32_t*)&b);
}

// ---------------- LayerNorm (fp16 out) ----------------
__global__ void __launch_bounds__(256) ln_kernel(const float* __restrict__ x,
                                                 const float* __restrict__ w,
                                                 const float* __restrict__ b,
                                                 __half* __restrict__ out) {
    int row = blockIdx.x;
    int t = threadIdx.x;
    const float4* xr = reinterpret_cast<const float4*>(x + (size_t)row * Dc);
    float4 v = xr[t];
    float s  = v.x + v.y + v.z + v.w;
    float ss = v.x * v.x + v.y * v.y + v.z * v.z + v.w * v.w;

    __shared__ float red0[8], red1[8];
    #pragma unroll
    for (int o = 16; o; o >>= 1) {
        s  += __shfl_xor_sync(0xffffffffu, s,  o);
        ss += __shfl_xor_sync(0xffffffffu, ss, o);
    }
    int wid = t >> 5, lid = t & 31;
    if (lid == 0) { red0[wid] = s; red1[wid] = ss; }
    __syncthreads();
    if (t == 0) {
        float a = 0.f, c = 0.f;
        #pragma unroll
        for (int i = 0; i < 8; i++) { a += red0[i]; c += red1[i]; }
        red0[0] = a; red1[0] = c;
    }
    __syncthreads();
    s = red0[0]; ss = red1[0];
    float mu   = s * (1.0f / Dc);
    float var  = ss * (1.0f / Dc) - mu * mu;
    float rstd = rsqrtf(var + 1e-5f);

    const float4* w4 = reinterpret_cast<const float4*>(w);
    const float4* b4 = reinterpret_cast<const float4*>(b);
    float4 ww = w4[t], bb = b4[t];
    half2 o0 = __float22half2_rn(make_float2((v.x - mu) * rstd * ww.x + bb.x,
                                             (v.y - mu) * rstd * ww.y + bb.y));
    half2 o1 = __float22half2_rn(make_float2((v.z - mu) * rstd * ww.z + bb.z,
                                             (v.w - mu) * rstd * ww.w + bb.w));
    ((uint2*)(out + (size_t)row * Dc))[t] = make_uint2(*(uint32_t*)&o0, *(uint32_t*)&o1);
}

// ---------------- RoPE ----------------
__global__ void rope_kernel(float* __restrict__ qkv) {
    int idx = blockIdx.x * blockDim.x + threadIdx.x;
    if (idx >= ROWS * Hc * (DHc / 2)) return;
    int j   = idx & 31;
    int h   = (idx >> 5) & (Hc - 1);
    int row = idx >> 9;
    int m   = row & (Mc - 1);

    float inv_freq = powf(10000.0f, -(float)(2 * j) / (float)DHc);
    float freq = (float)m * inv_freq;
    float sn, cs;
    sincosf(freq, &sn, &cs);

    float* qp = qkv + (size_t)row * QKVN + h * DHc;
    float* kp = qp + Dc;
    float q1 = qp[j], q2 = qp[32 + j];
    qp[j]      = q1 * cs - q2 * sn;
    qp[32 + j] = q1 * sn + q2 * cs;
    float k1 = kp[j], k2 = kp[32 + j];
    kp[j]      = k1 * cs - k2 * sn;
    kp[32 + j] = k1 * sn + k2 * cs;
}

// ---------------- Flash attention: 128x128 tiles, 8x8 register blocking (fp16 out) ----------------
#define PBS 136
#define F_QT 0
#define F_KT 8192
#define F_VS 16384
#define F_PB 24576
#define F_MSK (F_PB + 128 * PBS)
#define ATTN_SMEM_BYTES ((F_MSK + 128) * 4)

__global__ void __launch_bounds__(256) attn_kernel(const float* __restrict__ qkv,
                                                   const int* __restrict__ mask,
                                                   __half* __restrict__ out) {
    extern __shared__ __align__(16) float sh[];
    float* Qt = sh + F_QT;
    float* Kt = sh + F_KT;
    float* Vs = sh + F_VS;
    float* Pb = sh + F_PB;
    int*   msk = reinterpret_cast<int*>(sh + F_MSK);

    const int m0 = blockIdx.x * 128;
    const int h  = blockIdx.y;
    const int b  = blockIdx.z;
    const int t  = threadIdx.x;
    const int ty = t >> 4;
    const int tx = t & 15;

    const float* qbase = qkv + (size_t)(b * Mc + m0) * QKVN + h * DHc;
    const float* kbase = qkv + (size_t)(b * Mc) * QKVN + Dc + h * DHc;
    const float* vbase = kbase + Dc;
    const int*   mbase = mask + b * Mc;

    {
        const int r   = t & 127;
        const int sg0 = t >> 7;
        const float* qrow = qbase + (size_t)r * QKVN;
        #pragma unroll
        for (int sg = sg0; sg < 16; sg += 2) {
            float4 v = *(const float4*)(qrow + sg * 4);
            Qt[(sg * 4 + 0) * 128 + r] = v.x * 0.125f;
            Qt[(sg * 4 + 1) * 128 + r] = v.y * 0.125f;
            Qt[(sg * 4 + 2) * 128 + r] = v.z * 0.125f;
            Qt[(sg * 4 + 3) * 128 + r] = v.w * 0.125f;
        }
    }

    float mreg[8], lreg[8], oacc[8][4];
    #pragma unroll
    for (int i = 0; i < 8; i++) {
        mreg[i] = -1e30f; lreg[i] = 0.f;
        oacc[i][0] = oacc[i][1] = oacc[i][2] = oacc[i][3] = 0.f;
    }

    for (int n0 = 0; n0 < Mc; n0 += 128) {
        __syncthreads();
        int myv = 0;
        if (t < 128) { int mv = mbase[n0 + t]; msk[t] = mv; myv = (mv != 0); }
        int any = __syncthreads_or(myv);
        if (!any) continue;

        {
            const int r   = t & 127;
            const int sg0 = t >> 7;
            const float* krow = kbase + (size_t)(n0 + r) * QKVN;
            #pragma unroll
            for (int sg = sg0; sg < 16; sg += 2) {
                float4 v = *(const float4*)(krow + sg * 4);
                Kt[(sg * 4 + 0) * 128 + r] = v.x;
                Kt[(sg * 4 + 1) * 128 + r] = v.y;
                Kt[(sg * 4 + 2) * 128 + r] = v.z;
                Kt[(sg * 4 + 3) * 128 + r] = v.w;
            }
        }
        #pragma unroll
        for (int idx = t, it = 0; it < 8; idx += 256, it++) {
            int r = idx >> 4, sg = idx & 15;
            *(float4*)&Vs[r * 64 + sg * 4] =
                *(const float4*)(vbase + (size_t)(n0 + r) * QKVN + sg * 4);
        }
        __syncthreads();

        float s[8][8];
        #pragma unroll
        for (int i = 0; i < 8; i++)
            #pragma unroll
            for (int j = 0; j < 8; j++) s[i][j] = 0.f;

        #pragma unroll 4
        for (int d = 0; d < 64; d++) {
            float av[8], bv[8];
            *(float4*)(av)     = *(const float4*)&Qt[d * 128 + ty * 8];
            *(float4*)(av + 4) = *(const float4*)&Qt[d * 128 + ty * 8 + 4];
            *(float4*)(bv)     = *(const float4*)&Kt[d * 128 + tx * 8];
            *(float4*)(bv + 4) = *(const float4*)&Kt[d * 128 + tx * 8 + 4];
            #pragma unroll
            for (int i = 0; i < 8; i++)
                #pragma unroll
                for (int j = 0; j < 8; j++) s[i][j] += av[i] * bv[j];
        }

        bool val[8];
        #pragma unroll
        for (int j = 0; j < 8; j++) val[j] = (msk[tx * 8 + j] != 0);

        float scr[8];
        #pragma unroll
        for (int i = 0; i < 8; i++) {
            float tm = -1e30f;
            #pragma unroll
            for (int j = 0; j < 8; j++) if (val[j]) tm = fmaxf(tm, s[i][j]);
            tm = fmaxf(tm, __shfl_xor_sync(0xffffffffu, tm, 1));
            tm = fmaxf(tm, __shfl_xor_sync(0xffffffffu, tm, 2));
            tm = fmaxf(tm, __shfl_xor_sync(0xffffffffu, tm, 4));
            tm = fmaxf(tm, __shfl_xor_sync(0xffffffffu, tm, 8));
            float mn = fmaxf(mreg[i], tm);
            float sc = __expf(mreg[i] - mn);
            float rs = 0.f;
            #pragma unroll
            for (int j = 0; j < 8; j++) {
                float p = val[j] ? __expf(s[i][j] - mn) : 0.f;
                s[i][j] = p;
                rs += p;
            }
            rs += __shfl_xor_sync(0xffffffffu, rs, 1);
            rs += __shfl_xor_sync(0xffffffffu, rs, 2);
            rs += __shfl_xor_sync(0xffffffffu, rs, 4);
            rs += __shfl_xor_sync(0xffffffffu, rs, 8);
            lreg[i] = lreg[i] * sc + rs;
            mreg[i] = mn;
            scr[i]  = sc;
            *(float4*)&Pb[(ty * 8 + i) * PBS + tx * 8]     =
                make_float4(s[i][0], s[i][1], s[i][2], s[i][3]);
            *(float4*)&Pb[(ty * 8 + i) * PBS + tx * 8 + 4] =
                make_float4(s[i][4], s[i][5], s[i][6], s[i][7]);
        }
        __syncthreads();

        #pragma unroll
        for (int i = 0; i < 8; i++) {
            oacc[i][0] *= scr[i]; oacc[i][1] *= scr[i];
            oacc[i][2] *= scr[i]; oacc[i][3] *= scr[i];
        }
        #pragma unroll 2
        for (int kc = 0; kc < 128; kc += 4) {
            float4 v0 = *(const float4*)&Vs[(kc + 0) * 64 + tx * 4];
            float4 v1 = *(const float4*)&Vs[(kc + 1) * 64 + tx * 4];
            float4 v2 = *(const float4*)&Vs[(kc + 2) * 64 + tx * 4];
            float4 v3 = *(const float4*)&Vs[(kc + 3) * 64 + tx * 4];
            #pragma unroll
            for (int i = 0; i < 8; i++) {
                float4 p4 = *(const float4*)&Pb[(ty * 8 + i) * PBS + kc];
                oacc[i][0] += p4.x * v0.x; oacc[i][1] += p4.x * v0.y;
                oacc[i][2] += p4.x * v0.z; oacc[i][3] += p4.x * v0.w;
                oacc[i][0] += p4.y * v1.x; oacc[i][1] += p4.y * v1.y;
                oacc[i][2] += p4.y * v1.z; oacc[i][3] += p4.y * v1.w;
                oacc[i][0] += p4.z * v2.x; oacc[i][1] += p4.z * v2.y;
                oacc[i][2] += p4.z * v2.z; oacc[i][3] += p4.z * v2.w;
                oacc[i][0] += p4.w * v3.x; oacc[i][1] += p4.w * v3.y;
                oacc[i][2] += p4.w * v3.z; oacc[i][3] += p4.w * v3.w;
            }
        }
    }

    #pragma unroll
    for (int i = 0; i < 8; i++) {
        float inv = 1.0f / lreg[i];
        __half* op = out + (size_t)(b * Mc + m0 + ty * 8 + i) * Dc + h * DHc + tx * 4;
        half2 h0 = __float22half2_rn(make_float2(oacc[i][0] * inv, oacc[i][1] * inv));
        half2 h1 = __float22half2_rn(make_float2(oacc[i][2] * inv, oacc[i][3] * inv));
        *(uint2*)op = make_uint2(*(uint32_t*)&h0, *(uint32_t*)&h1);
    }
}

// ---------------- GeGLU (exact gelu * gate, fp16 out) ----------------
__global__ void geglu_kernel(const float* __restrict__ g, __half* __restrict__ act) {
    int idx = blockIdx.x * blockDim.x + threadIdx.x;
    if (idx >= ROWS * FFc) return;
    int r = idx / FFc;
    int j = idx - r * FFc;
    float x    = g[(size_t)r * WIN + j];
    float gate = g[(size_t)r * WIN + FFc + j];
    float ge = 0.5f * x * (1.0f + erff(x * 0.7071067811865476f));
    act[idx] = __float2half_rn(ge * gate);
}

// ---------------- launch ----------------
extern "C" void kernel_launch(void* const* d_in, const int* in_sizes, int n_in,
                              void* d_out, int out_size) {
    const float* x     = (const float*)d_in[0];
    const int*   mask  = (const int*)  d_in[1];
    const float* ln1w  = (const float*)d_in[2];
    const float* ln1b  = (const float*)d_in[3];
    const float* wqkv  = (const float*)d_in[4];
    const float* bqkv  = (const float*)d_in[5];
    const float* wo    = (const float*)d_in[6];
    const float* ln2w  = (const float*)d_in[7];
    const float* ln2b  = (const float*)d_in[8];
    const float* wi    = (const float*)d_in[9];
    const float* womlp = (const float*)d_in[10];
    float* out = (float*)d_out;

    float *qkvb, *x1, *gb;
    __half *xn, *attn, *hb, *actb, *wq, *wO, *wI, *wOM;
    cudaGetSymbolAddress((void**)&qkvb, g_qkv);
    cudaGetSymbolAddress((void**)&x1,   g_x1);
    cudaGetSymbolAddress((void**)&gb,   g_g);
    cudaGetSymbolAddress((void**)&xn,   h_xn);
    cudaGetSymbolAddress((void**)&attn, h_attn);
    cudaGetSymbolAddress((void**)&hb,   h_h);
    cudaGetSymbolAddress((void**)&actb, h_act);
    cudaGetSymbolAddress((void**)&wq,   hw_qkv);
    cudaGetSymbolAddress((void**)&wO,   hw_o);
    cudaGetSymbolAddress((void**)&wI,   hw_i);
    cudaGetSymbolAddress((void**)&wOM,  hw_om);

    cudaFuncSetAttribute(attn_kernel, cudaFuncAttributeMaxDynamicSharedMemorySize,
                         ATTN_SMEM_BYTES);

    // 0. weight conversions
    wcvt<<<(QKVN * Dc / 4 + 255) / 256, 256>>>(wqkv, wq, QKVN * Dc / 4);
    wcvt<<<(Dc * Dc / 4 + 255) / 256, 256>>>(wo, wO, Dc * Dc / 4);
    wcvt<<<((int)((size_t)WIN * Dc / 4) + 255) / 256, 256>>>(wi, wI, (int)((size_t)WIN * Dc / 4));
    wcvt<<<(Dc * FFc / 4 + 255) / 256, 256>>>(womlp, wOM, Dc * FFc / 4);

    // 1. LN1 -> fp16
    ln_kernel<<<ROWS, 256>>>(x, ln1w, ln1b, xn);
    // 2. QKV projection (+bias), fp32 out
    gemm_h2<<<dim3(QKVN / 128, ROWS / 128), 256>>>(xn, wq, bqkv, nullptr, qkvb, QKVN, Dc);
    // 3. RoPE
    rope_kernel<<<(ROWS * Hc * (DHc / 2) + 255) / 256, 256>>>(qkvb);
    // 4. Attention -> fp16
    attn_kernel<<<dim3(Mc / 128, Hc, Bc), 256, ATTN_SMEM_BYTES>>>(qkvb, mask, attn);
    // 5. WO projection + residual(x) -> fp32 x1
    gemm_h2<<<dim3(Dc / 128, ROWS / 128), 256>>>(attn, wO, nullptr, x, x1, Dc, Dc);
    // 6. LN2 -> fp16
    ln_kernel<<<ROWS, 256>>>(x1, ln2w, ln2b, hb);
    // 7. WI projection -> fp32 g
    gemm_h2<<<dim3(WIN / 128, ROWS / 128), 256>>>(hb, wI, nullptr, nullptr, gb, WIN, Dc);
    // 8. GeGLU -> fp16
    geglu_kernel<<<(ROWS * FFc + 255) / 256, 256>>>(gb, actb);
    // 9. WO_MLP projection + residual(x1) -> out
    gemm_h2<<<dim3(Dc / 128, ROWS / 128), 256>>>(actb, wOM, nullptr, x1, out, Dc, FFc);
}